// round 2
// baseline (speedup 1.0000x reference)
#include <cuda_runtime.h>
#include <math.h>
#include <stdint.h>

#define F 128
#define NMAX 100000
#define EMAX 1600000
#define BGR 8
#define CH 40

// ---------------- device scratch (no allocation allowed) ----------------
__device__ float g_y[NMAX * F];        // lin output
__device__ float g_aggr[NMAX * F];     // scatter-max accumulator
__device__ float g_h1[NMAX * F];       // sage output
__device__ float g_h2[80000 * F];      // pooled features
__device__ int   g_eA[2 * EMAX];
__device__ int   g_eB[2 * EMAX];
__device__ float g_s[NMAX];            // pooling scores
__device__ int   g_newpos[NMAX + 1];
__device__ int   g_gidx[80000];
__device__ float g_tanhv[80000];
__device__ unsigned g_thr[BGR];
__device__ int   g_needeq[BGR];
__device__ int   g_cnt[BGR];
__device__ int   g_eqcnt[BGR];
__device__ float g_wnorm;
__device__ float g_z[BGR * 2 * F];
__device__ float g_part[BGR * CH * 2 * F];

__device__ __forceinline__ unsigned ordkey(float f) {
    unsigned u = __float_as_uint(f);
    return (u & 0x80000000u) ? ~u : (u | 0x80000000u);
}

// ---------------- GEMM: C[M x 128] = relu(A1 @ W[:, :128]^T (+ A2 @ W[:,128:]^T) + bias)
// W row-major [128][K], K = KPARTS*128.
template <int KPARTS>
__global__ void k_gemm(const float* __restrict__ A1, const float* __restrict__ A2,
                       const float* __restrict__ W, const float* __restrict__ bias,
                       float* __restrict__ C, float* __restrict__ Caux, int M)
{
    __shared__ float sA[16][132];
    __shared__ float sB[16][132];
    const int tid = threadIdx.x;
    const int tx = tid & 15, ty = tid >> 4;
    const int r0 = blockIdx.x * 128;
    const int K = KPARTS * 128;

    float acc[8][8];
#pragma unroll
    for (int i = 0; i < 8; i++)
#pragma unroll
        for (int j = 0; j < 8; j++) acc[i][j] = 0.f;

    for (int kk0 = 0; kk0 < K; kk0 += 16) {
        const float* Asrc = A1;
        int acol = kk0;
        if (KPARTS == 2 && kk0 >= 128) { Asrc = A2; acol = kk0 - 128; }
#pragma unroll
        for (int l = 0; l < 2; l++) {
            int id = tid + l * 256;          // 0..511
            int row = id >> 2;               // 0..127
            int kc = (id & 3) * 4;           // 0,4,8,12
            int gr = r0 + row;
            float4 v = make_float4(0.f, 0.f, 0.f, 0.f);
            if (gr < M) v = *(const float4*)(Asrc + (size_t)gr * F + acol + kc);
            sA[kc + 0][row] = v.x; sA[kc + 1][row] = v.y;
            sA[kc + 2][row] = v.z; sA[kc + 3][row] = v.w;
        }
#pragma unroll
        for (int l = 0; l < 2; l++) {
            int id = tid + l * 256;
            int nrow = id >> 2;
            int kc = (id & 3) * 4;
            float4 v = *(const float4*)(W + (size_t)nrow * K + kk0 + kc);
            sB[kc + 0][nrow] = v.x; sB[kc + 1][nrow] = v.y;
            sB[kc + 2][nrow] = v.z; sB[kc + 3][nrow] = v.w;
        }
        __syncthreads();
#pragma unroll
        for (int k = 0; k < 16; k++) {
            float ra[8], rb[8];
#pragma unroll
            for (int i = 0; i < 8; i++) ra[i] = sA[k][ty * 8 + i];
#pragma unroll
            for (int j = 0; j < 8; j++) rb[j] = sB[k][tx * 8 + j];
#pragma unroll
            for (int i = 0; i < 8; i++)
#pragma unroll
                for (int j = 0; j < 8; j++)
                    acc[i][j] = fmaf(ra[i], rb[j], acc[i][j]);
        }
        __syncthreads();
    }
#pragma unroll
    for (int i = 0; i < 8; i++) {
        int gr = r0 + ty * 8 + i;
        if (gr >= M) continue;
#pragma unroll
        for (int j = 0; j < 8; j++) {
            int gc = tx * 8 + j;
            float v = acc[i][j] + (bias ? bias[gc] : 0.f);
            v = fmaxf(v, 0.f);
            C[(size_t)gr * F + gc] = v;
            if (Caux) Caux[(size_t)gr * F + gc] = v;
        }
    }
}

// ---------------- edge scatter-max (values >= 0 -> int atomicMax is exact)
__global__ void k_scatter(const int* __restrict__ esrc, const int* __restrict__ edst,
                          const float* __restrict__ y, float* __restrict__ aggr,
                          int E, int dummy)
{
    int gtid = blockIdx.x * blockDim.x + threadIdx.x;
    int eid = gtid >> 5;
    int lane = threadIdx.x & 31;
    if (eid >= E) return;
    int d = edst[eid];
    if (d >= dummy) return;
    int s = esrc[eid];
    float4 v = *(const float4*)(y + (size_t)s * F + lane * 4);
    float* ab = aggr + (size_t)d * F + lane * 4;
    float4 cur = *(const float4*)ab;
    int* ap = (int*)ab;
    if (v.x > cur.x) atomicMax(ap + 0, __float_as_int(v.x));
    if (v.y > cur.y) atomicMax(ap + 1, __float_as_int(v.y));
    if (v.z > cur.z) atomicMax(ap + 2, __float_as_int(v.z));
    if (v.w > cur.w) atomicMax(ap + 3, __float_as_int(v.w));
}

// ---------------- ||w|| ----------------
__global__ void k_wnorm(const float* __restrict__ w)
{
    __shared__ float red[4];
    int t = threadIdx.x;  // 128 threads
    float v = w[t];
    float sq = v * v;
    for (int o = 16; o > 0; o >>= 1) sq += __shfl_down_sync(0xffffffffu, sq, o);
    if ((t & 31) == 0) red[t >> 5] = sq;
    __syncthreads();
    if (t == 0) g_wnorm = sqrtf(red[0] + red[1] + red[2] + red[3]);
}

// ---------------- scores: s[v] = h[v].w / ||w||  (warp per node) ----------------
__global__ void k_scores(const float* __restrict__ h, const float* __restrict__ w, int M)
{
    int warp = blockIdx.x * (blockDim.x >> 5) + (threadIdx.x >> 5);
    int lane = threadIdx.x & 31;
    if (warp >= M) return;
    float4 a = ((const float4*)(h + (size_t)warp * F))[lane];
    float4 b = ((const float4*)w)[lane];
    float d = a.x * b.x + a.y * b.y + a.z * b.z + a.w * b.w;
    for (int o = 16; o > 0; o >>= 1) d += __shfl_down_sync(0xffffffffu, d, o);
    if (lane == 0) g_s[warp] = d / g_wnorm;
}

// ---------------- per-graph exact radix select of k-th largest score ----------------
__global__ void k_select(int n, int kk)
{
    int g = blockIdx.x;
    const float* sg = g_s + (size_t)g * n;
    __shared__ unsigned hist[256];
    __shared__ unsigned s_prefix, s_mask;
    __shared__ int s_need;
    if (threadIdx.x == 0) { s_prefix = 0; s_mask = 0; s_need = kk; }
    __syncthreads();
    for (int pass = 0; pass < 4; ++pass) {
        int shift = 24 - 8 * pass;
        if (threadIdx.x < 256) hist[threadIdx.x] = 0;
        __syncthreads();
        unsigned pre = s_prefix, msk = s_mask;
        for (int i = threadIdx.x; i < n; i += blockDim.x) {
            unsigned key = ordkey(sg[i]);
            if ((key & msk) == pre) atomicAdd(&hist[(key >> shift) & 255], 1u);
        }
        __syncthreads();
        if (threadIdx.x == 0) {
            int need = s_need;
            unsigned cum = 0;
            for (int b = 255; b >= 0; --b) {
                unsigned h = hist[b];
                if (cum + h >= (unsigned)need) {
                    s_need = need - (int)cum;
                    s_prefix = pre | ((unsigned)b << shift);
                    s_mask = msk | (255u << shift);
                    break;
                }
                cum += h;
            }
        }
        __syncthreads();
    }
    if (threadIdx.x == 0) { g_thr[g] = s_prefix; g_needeq[g] = s_need; }
}

__global__ void k_initpool(int Msize, int Mn)
{
    int i = blockIdx.x * blockDim.x + threadIdx.x;
    if (i < Msize) g_newpos[i] = Mn;
    if (i < BGR) { g_cnt[i] = 0; g_eqcnt[i] = 0; }
}

__global__ void k_compact(int M, int n, int kk)
{
    int v = blockIdx.x * blockDim.x + threadIdx.x;
    if (v >= M) return;
    int g = v / n;
    float sv = g_s[v];
    unsigned key = ordkey(sv);
    unsigned T = g_thr[g];
    bool keep = false;
    if (key > T) keep = true;
    else if (key == T && atomicAdd(&g_eqcnt[g], 1) < g_needeq[g]) keep = true;
    if (!keep) return;
    int pos = atomicAdd(&g_cnt[g], 1);
    int j = g * kk + pos;
    g_newpos[v] = j;
    g_gidx[j] = v;
    g_tanhv[j] = tanhf(sv);
}

__global__ void k_gather(const float* __restrict__ h, float* __restrict__ xnew, int Mn)
{
    int idx = blockIdx.x * blockDim.x + threadIdx.x;
    int j = idx >> 5, q = idx & 31;
    if (j >= Mn) return;
    float t = g_tanhv[j];
    float4 v = *(const float4*)(h + (size_t)g_gidx[j] * F + q * 4);
    v.x *= t; v.y *= t; v.z *= t; v.w *= t;
    *(float4*)(xnew + (size_t)j * F + q * 4) = v;
}

__global__ void k_remap(const int* __restrict__ es, const int* __restrict__ ed,
                        int* __restrict__ eo, int E, int Mn)
{
    int i = blockIdx.x * blockDim.x + threadIdx.x;
    if (i >= E) return;
    int s = g_newpos[es[i]];
    int d = g_newpos[ed[i]];
    if (s == Mn || d == Mn) { s = Mn; d = Mn; }
    eo[i] = s;
    eo[E + i] = d;
}

// ---------------- readout: per-graph max & mean, chunked partials ----------------
__global__ void k_rpart(const float* __restrict__ x, int kk)
{
    int g = blockIdx.x / CH, c = blockIdx.x % CH;
    int rpc = kk / CH;  // exact for 10000/8000/6400
    int f = threadIdx.x;  // 128
    const float* base = x + ((size_t)g * kk + (size_t)c * rpc) * F + f;
    float vmax = -3.4e38f, vsum = 0.f;
    for (int r = 0; r < rpc; r++) {
        float v = base[(size_t)r * F];
        vmax = fmaxf(vmax, v);
        vsum += v;
    }
    float* p = g_part + (size_t)blockIdx.x * 2 * F;
    p[f] = vmax;
    p[F + f] = vsum;
}

__global__ void k_rfinal(int kk)
{
    int g = blockIdx.x;
    int f = threadIdx.x;  // 256
    const float* p = g_part + (size_t)g * CH * 2 * F;
    if (f < F) {
        float m = -3.4e38f;
        for (int c = 0; c < CH; c++) m = fmaxf(m, p[c * 2 * F + f]);
        g_z[g * 2 * F + f] += m;
    } else {
        float s = 0.f;
        for (int c = 0; c < CH; c++) s += p[c * 2 * F + f];
        g_z[g * 2 * F + f] += s / (float)kk;
    }
}

__global__ void k_zeroz()
{
    int i = blockIdx.x * blockDim.x + threadIdx.x;
    if (i < BGR * 2 * F) g_z[i] = 0.f;
}

// ---------------- final MLP + sigmoid ----------------
__global__ void k_mlp(const float* __restrict__ Wl1, const float* __restrict__ bl1,
                      const float* __restrict__ Wl2, const float* __restrict__ bl2,
                      const float* __restrict__ Wl3, const float* __restrict__ bl3,
                      float* __restrict__ out)
{
    __shared__ float sz[BGR][2 * F];
    __shared__ float h1[BGR][F];
    __shared__ float h2[BGR][64];
    int t = threadIdx.x;  // 256
    for (int i = t; i < BGR * 2 * F; i += 256) ((float*)sz)[i] = g_z[i];
    __syncthreads();
    for (int o = t; o < BGR * F; o += 256) {
        int g = o >> 7, r = o & 127;
        float a = bl1[r];
        const float* wr = Wl1 + (size_t)r * 2 * F;
        for (int c = 0; c < 2 * F; c++) a += sz[g][c] * wr[c];
        h1[g][r] = fmaxf(a, 0.f);
    }
    __syncthreads();
    for (int o = t; o < BGR * 64; o += 256) {
        int g = o >> 6, r = o & 63;
        float a = bl2[r];
        const float* wr = Wl2 + (size_t)r * F;
        for (int c = 0; c < F; c++) a += h1[g][c] * wr[c];
        h2[g][r] = fmaxf(a, 0.f);
    }
    __syncthreads();
    if (t < BGR) {
        float a = bl3[0];
        for (int c = 0; c < 64; c++) a += h2[t][c] * Wl3[c];
        out[t] = 1.f / (1.f + expf(-a));
    }
}

// ---------------- orchestration ----------------
extern "C" void kernel_launch(void* const* d_in, const int* in_sizes, int n_in,
                              void* d_out, int out_size)
{
    const float* x = (const float*)d_in[0];
    const int* ei = (const int*)d_in[1];
    const float* Wlin[3] = { (const float*)d_in[2], (const float*)d_in[6], (const float*)d_in[10] };
    const float* blin[3] = { (const float*)d_in[3], (const float*)d_in[7], (const float*)d_in[11] };
    const float* Wupd[3] = { (const float*)d_in[4], (const float*)d_in[8], (const float*)d_in[12] };
    const float* wp[3]   = { (const float*)d_in[5], (const float*)d_in[9], (const float*)d_in[13] };
    const float* Wl1 = (const float*)d_in[14];
    const float* bl1 = (const float*)d_in[15];
    const float* Wl2 = (const float*)d_in[16];
    const float* bl2 = (const float*)d_in[17];
    const float* Wl3 = (const float*)d_in[18];
    const float* bl3 = (const float*)d_in[19];

    float *yb, *ag, *h1p, *h2p;
    int *eA, *eB;
    cudaGetSymbolAddress((void**)&yb, g_y);
    cudaGetSymbolAddress((void**)&ag, g_aggr);
    cudaGetSymbolAddress((void**)&h1p, g_h1);
    cudaGetSymbolAddress((void**)&h2p, g_h2);
    cudaGetSymbolAddress((void**)&eA, g_eA);
    cudaGetSymbolAddress((void**)&eB, g_eB);

    const int Ms[3] = { 100000, 80000, 64000 };
    const int kks[3] = { 10000, 8000, 6400 };

    // zero the full 2048-element z accumulator (8 blocks x 256 threads)
    k_zeroz<<<8, 256>>>();

    const float* hin = x;
    const int* es = ei;
    const int* ed = ei + EMAX;

    for (int st = 0; st < 3; ++st) {
        int M = Ms[st];
        int gridG = (M + 127) / 128;

        // SAGEConv
        k_gemm<1><<<gridG, 256>>>(hin, nullptr, Wlin[st], blin[st], yb, ag, M);
        k_scatter<<<EMAX / 8, 256>>>(es, ed, yb, ag, EMAX, M);
        k_gemm<2><<<gridG, 256>>>(ag, hin, Wupd[st], nullptr, h1p, nullptr, M);

        // TopK pool
        int kk = kks[st], n = M / BGR, Mn = BGR * kk;
        k_wnorm<<<1, 128>>>(wp[st]);
        k_scores<<<(M + 3) / 4, 128>>>(h1p, wp[st], M);
        k_select<<<BGR, 256>>>(n, kk);
        k_initpool<<<(M + 1 + 255) / 256, 256>>>(M + 1, Mn);
        k_compact<<<(M + 255) / 256, 256>>>(M, n, kk);
        k_gather<<<(Mn * 32 + 255) / 256, 256>>>(h1p, h2p, Mn);
        if (st < 2) {
            int* eo = (st == 0) ? eA : eB;
            k_remap<<<(EMAX + 255) / 256, 256>>>(es, ed, eo, EMAX, Mn);
            es = eo;
            ed = eo + EMAX;
        }

        // readout (accumulate into z)
        k_rpart<<<BGR * CH, 128>>>(h2p, kk);
        k_rfinal<<<BGR, 256>>>(kk);

        hin = h2p;
    }

    k_mlp<<<1, 256>>>(Wl1, bl1, Wl2, bl2, Wl3, bl3, (float*)d_out);
}

// round 3
// speedup vs baseline: 1.4325x; 1.4325x over previous
#include <cuda_runtime.h>
#include <math.h>
#include <stdint.h>

#define F 128
#define NMAX 100000
#define EMAX 1600000
#define BGR 8
#define CH 40
#define CAPD 96

// ---------------- device scratch (no allocation allowed) ----------------
__device__ float g_y[NMAX * F];        // lin output
__device__ float g_aggr[NMAX * F];     // gather-max result
__device__ float g_h1[NMAX * F];       // sage output
__device__ float g_h2[80000 * F];      // pooled features
__device__ int   g_eA[2 * EMAX];
__device__ int   g_eB[2 * EMAX];
__device__ int   g_deg[NMAX];          // per-dst incoming count
__device__ int   g_bkt[NMAX * CAPD];   // per-dst src buckets
__device__ float g_s[NMAX];            // pooling scores
__device__ int   g_newpos[NMAX + 1];
__device__ int   g_gidx[80000];
__device__ float g_tanhv[80000];
__device__ unsigned g_thr[BGR];
__device__ int   g_needeq[BGR];
__device__ int   g_cnt[BGR];
__device__ int   g_eqcnt[BGR];
__device__ float g_wnorm;
__device__ float g_z[BGR * 2 * F];
__device__ float g_part[BGR * CH * 2 * F];

__device__ __forceinline__ unsigned ordkey(float f) {
    unsigned u = __float_as_uint(f);
    return (u & 0x80000000u) ? ~u : (u | 0x80000000u);
}

// ---------------- GEMM: C[M x 128] = relu(A1 @ W[:, :128]^T (+ A2 @ W[:,128:]^T) + bias)
template <int KPARTS>
__global__ void k_gemm(const float* __restrict__ A1, const float* __restrict__ A2,
                       const float* __restrict__ W, const float* __restrict__ bias,
                       float* __restrict__ C, int M)
{
    __shared__ float sA[16][132];
    __shared__ float sB[16][132];
    const int tid = threadIdx.x;
    const int tx = tid & 15, ty = tid >> 4;
    const int r0 = blockIdx.x * 128;
    const int K = KPARTS * 128;

    float acc[8][8];
#pragma unroll
    for (int i = 0; i < 8; i++)
#pragma unroll
        for (int j = 0; j < 8; j++) acc[i][j] = 0.f;

    for (int kk0 = 0; kk0 < K; kk0 += 16) {
        const float* Asrc = A1;
        int acol = kk0;
        if (KPARTS == 2 && kk0 >= 128) { Asrc = A2; acol = kk0 - 128; }
#pragma unroll
        for (int l = 0; l < 2; l++) {
            int id = tid + l * 256;
            int row = id >> 2;
            int kc = (id & 3) * 4;
            int gr = r0 + row;
            float4 v = make_float4(0.f, 0.f, 0.f, 0.f);
            if (gr < M) v = *(const float4*)(Asrc + (size_t)gr * F + acol + kc);
            sA[kc + 0][row] = v.x; sA[kc + 1][row] = v.y;
            sA[kc + 2][row] = v.z; sA[kc + 3][row] = v.w;
        }
#pragma unroll
        for (int l = 0; l < 2; l++) {
            int id = tid + l * 256;
            int nrow = id >> 2;
            int kc = (id & 3) * 4;
            float4 v = *(const float4*)(W + (size_t)nrow * K + kk0 + kc);
            sB[kc + 0][nrow] = v.x; sB[kc + 1][nrow] = v.y;
            sB[kc + 2][nrow] = v.z; sB[kc + 3][nrow] = v.w;
        }
        __syncthreads();
#pragma unroll
        for (int k = 0; k < 16; k++) {
            float ra[8], rb[8];
#pragma unroll
            for (int i = 0; i < 8; i++) ra[i] = sA[k][ty * 8 + i];
#pragma unroll
            for (int j = 0; j < 8; j++) rb[j] = sB[k][tx * 8 + j];
#pragma unroll
            for (int i = 0; i < 8; i++)
#pragma unroll
                for (int j = 0; j < 8; j++)
                    acc[i][j] = fmaf(ra[i], rb[j], acc[i][j]);
        }
        __syncthreads();
    }
#pragma unroll
    for (int i = 0; i < 8; i++) {
        int gr = r0 + ty * 8 + i;
        if (gr >= M) continue;
#pragma unroll
        for (int j = 0; j < 8; j++) {
            int gc = tx * 8 + j;
            float v = acc[i][j] + (bias ? bias[gc] : 0.f);
            C[(size_t)gr * F + gc] = fmaxf(v, 0.f);
        }
    }
}

// ---------------- CSR-bucket build: deg-zero, then hist+scatter ----------------
__global__ void k_zerodeg(int M)
{
    int i = blockIdx.x * blockDim.x + threadIdx.x;
    if (i < M) g_deg[i] = 0;
}

__global__ void k_bucket(const int* __restrict__ esrc, const int* __restrict__ edst,
                         int E, int M)
{
    int e = blockIdx.x * blockDim.x + threadIdx.x;
    if (e >= E) return;
    int d = edst[e];
    if (d >= M) return;               // dummy-routed edge
    int s = esrc[e];
    int pos = atomicAdd(&g_deg[d], 1);
    if (pos < CAPD) g_bkt[(size_t)d * CAPD + pos] = s;
}

// ---------------- gather-max: warp per dst node, no atomics ----------------
__global__ void k_aggr(const float* __restrict__ y, float* __restrict__ aggr, int M)
{
    int warp = blockIdx.x * (blockDim.x >> 5) + (threadIdx.x >> 5);
    int lane = threadIdx.x & 31;
    if (warp >= M) return;
    int dv = g_deg[warp];
    if (dv > CAPD) dv = CAPD;
    const int* b = g_bkt + (size_t)warp * CAPD;
    // self loop: start from y[v]
    float4 acc = ((const float4*)(y + (size_t)warp * F))[lane];
    int i = 0;
    for (; i + 1 < dv; i += 2) {
        int s0 = b[i], s1 = b[i + 1];
        float4 t0 = ((const float4*)(y + (size_t)s0 * F))[lane];
        float4 t1 = ((const float4*)(y + (size_t)s1 * F))[lane];
        acc.x = fmaxf(acc.x, fmaxf(t0.x, t1.x));
        acc.y = fmaxf(acc.y, fmaxf(t0.y, t1.y));
        acc.z = fmaxf(acc.z, fmaxf(t0.z, t1.z));
        acc.w = fmaxf(acc.w, fmaxf(t0.w, t1.w));
    }
    if (i < dv) {
        int s0 = b[i];
        float4 t0 = ((const float4*)(y + (size_t)s0 * F))[lane];
        acc.x = fmaxf(acc.x, t0.x);
        acc.y = fmaxf(acc.y, t0.y);
        acc.z = fmaxf(acc.z, t0.z);
        acc.w = fmaxf(acc.w, t0.w);
    }
    ((float4*)(aggr + (size_t)warp * F))[lane] = acc;
}

// ---------------- ||w|| ----------------
__global__ void k_wnorm(const float* __restrict__ w)
{
    __shared__ float red[4];
    int t = threadIdx.x;  // 128 threads
    float v = w[t];
    float sq = v * v;
    for (int o = 16; o > 0; o >>= 1) sq += __shfl_down_sync(0xffffffffu, sq, o);
    if ((t & 31) == 0) red[t >> 5] = sq;
    __syncthreads();
    if (t == 0) g_wnorm = sqrtf(red[0] + red[1] + red[2] + red[3]);
}

// ---------------- scores ----------------
__global__ void k_scores(const float* __restrict__ h, const float* __restrict__ w, int M)
{
    int warp = blockIdx.x * (blockDim.x >> 5) + (threadIdx.x >> 5);
    int lane = threadIdx.x & 31;
    if (warp >= M) return;
    float4 a = ((const float4*)(h + (size_t)warp * F))[lane];
    float4 b = ((const float4*)w)[lane];
    float d = a.x * b.x + a.y * b.y + a.z * b.z + a.w * b.w;
    for (int o = 16; o > 0; o >>= 1) d += __shfl_down_sync(0xffffffffu, d, o);
    if (lane == 0) g_s[warp] = d / g_wnorm;
}

// ---------------- per-graph exact radix select ----------------
__global__ void k_select(int n, int kk)
{
    int g = blockIdx.x;
    const float* sg = g_s + (size_t)g * n;
    __shared__ unsigned hist[256];
    __shared__ unsigned s_prefix, s_mask;
    __shared__ int s_need;
    if (threadIdx.x == 0) { s_prefix = 0; s_mask = 0; s_need = kk; }
    __syncthreads();
    for (int pass = 0; pass < 4; ++pass) {
        int shift = 24 - 8 * pass;
        if (threadIdx.x < 256) hist[threadIdx.x] = 0;
        __syncthreads();
        unsigned pre = s_prefix, msk = s_mask;
        for (int i = threadIdx.x; i < n; i += blockDim.x) {
            unsigned key = ordkey(sg[i]);
            if ((key & msk) == pre) atomicAdd(&hist[(key >> shift) & 255], 1u);
        }
        __syncthreads();
        if (threadIdx.x == 0) {
            int need = s_need;
            unsigned cum = 0;
            for (int b = 255; b >= 0; --b) {
                unsigned h = hist[b];
                if (cum + h >= (unsigned)need) {
                    s_need = need - (int)cum;
                    s_prefix = pre | ((unsigned)b << shift);
                    s_mask = msk | (255u << shift);
                    break;
                }
                cum += h;
            }
        }
        __syncthreads();
    }
    if (threadIdx.x == 0) { g_thr[g] = s_prefix; g_needeq[g] = s_need; }
}

__global__ void k_initpool(int Msize, int Mn)
{
    int i = blockIdx.x * blockDim.x + threadIdx.x;
    if (i < Msize) g_newpos[i] = Mn;
    if (i < BGR) { g_cnt[i] = 0; g_eqcnt[i] = 0; }
}

__global__ void k_compact(int M, int n, int kk)
{
    int v = blockIdx.x * blockDim.x + threadIdx.x;
    if (v >= M) return;
    int g = v / n;
    float sv = g_s[v];
    unsigned key = ordkey(sv);
    unsigned T = g_thr[g];
    bool keep = false;
    if (key > T) keep = true;
    else if (key == T && atomicAdd(&g_eqcnt[g], 1) < g_needeq[g]) keep = true;
    if (!keep) return;
    int pos = atomicAdd(&g_cnt[g], 1);
    int j = g * kk + pos;
    g_newpos[v] = j;
    g_gidx[j] = v;
    g_tanhv[j] = tanhf(sv);
}

__global__ void k_gather(const float* __restrict__ h, float* __restrict__ xnew, int Mn)
{
    int idx = blockIdx.x * blockDim.x + threadIdx.x;
    int j = idx >> 5, q = idx & 31;
    if (j >= Mn) return;
    float t = g_tanhv[j];
    float4 v = *(const float4*)(h + (size_t)g_gidx[j] * F + q * 4);
    v.x *= t; v.y *= t; v.z *= t; v.w *= t;
    *(float4*)(xnew + (size_t)j * F + q * 4) = v;
}

__global__ void k_remap(const int* __restrict__ es, const int* __restrict__ ed,
                        int* __restrict__ eo, int E, int Mn)
{
    int i = blockIdx.x * blockDim.x + threadIdx.x;
    if (i >= E) return;
    int s = g_newpos[es[i]];
    int d = g_newpos[ed[i]];
    if (s == Mn || d == Mn) { s = Mn; d = Mn; }
    eo[i] = s;
    eo[E + i] = d;
}

// ---------------- readout ----------------
__global__ void k_rpart(const float* __restrict__ x, int kk)
{
    int g = blockIdx.x / CH, c = blockIdx.x % CH;
    int rpc = kk / CH;
    int f = threadIdx.x;  // 128
    const float* base = x + ((size_t)g * kk + (size_t)c * rpc) * F + f;
    float vmax = -3.4e38f, vsum = 0.f;
    for (int r = 0; r < rpc; r++) {
        float v = base[(size_t)r * F];
        vmax = fmaxf(vmax, v);
        vsum += v;
    }
    float* p = g_part + (size_t)blockIdx.x * 2 * F;
    p[f] = vmax;
    p[F + f] = vsum;
}

__global__ void k_rfinal(int kk)
{
    int g = blockIdx.x;
    int f = threadIdx.x;  // 256
    const float* p = g_part + (size_t)g * CH * 2 * F;
    if (f < F) {
        float m = -3.4e38f;
        for (int c = 0; c < CH; c++) m = fmaxf(m, p[c * 2 * F + f]);
        g_z[g * 2 * F + f] += m;
    } else {
        float s = 0.f;
        for (int c = 0; c < CH; c++) s += p[c * 2 * F + f];
        g_z[g * 2 * F + f] += s / (float)kk;
    }
}

__global__ void k_zeroz()
{
    int i = blockIdx.x * blockDim.x + threadIdx.x;
    if (i < BGR * 2 * F) g_z[i] = 0.f;
}

// ---------------- final MLP + sigmoid ----------------
__global__ void k_mlp(const float* __restrict__ Wl1, const float* __restrict__ bl1,
                      const float* __restrict__ Wl2, const float* __restrict__ bl2,
                      const float* __restrict__ Wl3, const float* __restrict__ bl3,
                      float* __restrict__ out)
{
    __shared__ float sz[BGR][2 * F];
    __shared__ float h1[BGR][F];
    __shared__ float h2[BGR][64];
    int t = threadIdx.x;  // 256
    for (int i = t; i < BGR * 2 * F; i += 256) ((float*)sz)[i] = g_z[i];
    __syncthreads();
    for (int o = t; o < BGR * F; o += 256) {
        int g = o >> 7, r = o & 127;
        float a = bl1[r];
        const float* wr = Wl1 + (size_t)r * 2 * F;
        for (int c = 0; c < 2 * F; c++) a += sz[g][c] * wr[c];
        h1[g][r] = fmaxf(a, 0.f);
    }
    __syncthreads();
    for (int o = t; o < BGR * 64; o += 256) {
        int g = o >> 6, r = o & 63;
        float a = bl2[r];
        const float* wr = Wl2 + (size_t)r * F;
        for (int c = 0; c < F; c++) a += h1[g][c] * wr[c];
        h2[g][r] = fmaxf(a, 0.f);
    }
    __syncthreads();
    if (t < BGR) {
        float a = bl3[0];
        for (int c = 0; c < 64; c++) a += h2[t][c] * Wl3[c];
        out[t] = 1.f / (1.f + expf(-a));
    }
}

// ---------------- orchestration ----------------
extern "C" void kernel_launch(void* const* d_in, const int* in_sizes, int n_in,
                              void* d_out, int out_size)
{
    const float* x = (const float*)d_in[0];
    const int* ei = (const int*)d_in[1];
    const float* Wlin[3] = { (const float*)d_in[2], (const float*)d_in[6], (const float*)d_in[10] };
    const float* blin[3] = { (const float*)d_in[3], (const float*)d_in[7], (const float*)d_in[11] };
    const float* Wupd[3] = { (const float*)d_in[4], (const float*)d_in[8], (const float*)d_in[12] };
    const float* wp[3]   = { (const float*)d_in[5], (const float*)d_in[9], (const float*)d_in[13] };
    const float* Wl1 = (const float*)d_in[14];
    const float* bl1 = (const float*)d_in[15];
    const float* Wl2 = (const float*)d_in[16];
    const float* bl2 = (const float*)d_in[17];
    const float* Wl3 = (const float*)d_in[18];
    const float* bl3 = (const float*)d_in[19];

    float *yb, *ag, *h1p, *h2p;
    int *eA, *eB;
    cudaGetSymbolAddress((void**)&yb, g_y);
    cudaGetSymbolAddress((void**)&ag, g_aggr);
    cudaGetSymbolAddress((void**)&h1p, g_h1);
    cudaGetSymbolAddress((void**)&h2p, g_h2);
    cudaGetSymbolAddress((void**)&eA, g_eA);
    cudaGetSymbolAddress((void**)&eB, g_eB);

    const int Ms[3] = { 100000, 80000, 64000 };
    const int kks[3] = { 10000, 8000, 6400 };

    k_zeroz<<<8, 256>>>();

    const float* hin = x;
    const int* es = ei;
    const int* ed = ei + EMAX;

    for (int st = 0; st < 3; ++st) {
        int M = Ms[st];
        int gridG = (M + 127) / 128;

        // SAGEConv: lin + CSR-bucketed gather-max + update
        k_gemm<1><<<gridG, 256>>>(hin, nullptr, Wlin[st], blin[st], yb, M);
        k_zerodeg<<<(M + 255) / 256, 256>>>(M);
        k_bucket<<<(EMAX + 255) / 256, 256>>>(es, ed, EMAX, M);
        k_aggr<<<(M + 7) / 8, 256>>>(yb, ag, M);
        k_gemm<2><<<gridG, 256>>>(ag, hin, Wupd[st], nullptr, h1p, M);

        // TopK pool
        int kk = kks[st], n = M / BGR, Mn = BGR * kk;
        k_wnorm<<<1, 128>>>(wp[st]);
        k_scores<<<(M + 3) / 4, 128>>>(h1p, wp[st], M);
        k_select<<<BGR, 256>>>(n, kk);
        k_initpool<<<(M + 1 + 255) / 256, 256>>>(M + 1, Mn);
        k_compact<<<(M + 255) / 256, 256>>>(M, n, kk);
        k_gather<<<(Mn * 32 + 255) / 256, 256>>>(h1p, h2p, Mn);
        if (st < 2) {
            int* eo = (st == 0) ? eA : eB;
            k_remap<<<(EMAX + 255) / 256, 256>>>(es, ed, eo, EMAX, Mn);
            es = eo;
            ed = eo + EMAX;
        }

        // readout (accumulate into z)
        k_rpart<<<BGR * CH, 128>>>(h2p, kk);
        k_rfinal<<<BGR, 256>>>(kk);

        hin = h2p;
    }

    k_mlp<<<1, 256>>>(Wl1, bl1, Wl2, bl2, Wl3, bl3, (float*)d_out);
}

// round 4
// speedup vs baseline: 1.5002x; 1.0472x over previous
#include <cuda_runtime.h>
#include <math.h>
#include <stdint.h>

#define F 128
#define NMAX 100000
#define EMAX 1600000
#define BGR 8
#define CH 40
#define CAPD 96

// ---------------- device scratch ----------------
__device__ float g_y[NMAX * F];
__device__ float g_aggr[NMAX * F];
__device__ float g_h1[NMAX * F];
__device__ float g_h2[80000 * F];
__device__ int   g_eA[2 * EMAX];
__device__ int   g_eB[2 * EMAX];
__device__ int   g_deg[NMAX];
__device__ int   g_bkt[NMAX * CAPD];
__device__ float g_s[NMAX];
__device__ int   g_newpos[NMAX + 1];
__device__ int   g_gidx[80000];
__device__ float g_tanhv[80000];
__device__ unsigned g_thr[BGR];
__device__ int   g_needeq[BGR];
__device__ int   g_cnt[BGR];
__device__ int   g_eqcnt[BGR];
__device__ float g_z[BGR * 2 * F];
__device__ float g_part[BGR * CH * 2 * F];

__device__ __forceinline__ unsigned ordkey(float f) {
    unsigned u = __float_as_uint(f);
    return (u & 0x80000000u) ? ~u : (u | 0x80000000u);
}

// ---------------- GEMM: C[M x 128] = relu(A1 @ W[:, :128]^T (+ A2 @ W[:,128:]^T) + bias)
// Double-buffered smem, float4 fragments, 1 barrier per k-step.
template <int KPARTS>
__global__ __launch_bounds__(256)
void k_gemm(const float* __restrict__ A1, const float* __restrict__ A2,
            const float* __restrict__ W, const float* __restrict__ bias,
            float* __restrict__ C, int M)
{
    __shared__ float sA[2][16][132];
    __shared__ float sB[2][16][132];
    const int tid = threadIdx.x;
    const int tx = tid & 15, ty = tid >> 4;
    const int r0 = blockIdx.x * 128;
    const int K = KPARTS * 128;
    const int NSTEP = KPARTS * 8;

    // per-thread load coordinates (2 chunks per buffer)
    const int rowA0 = tid >> 2,          kcA0 = (tid & 3) * 4;
    const int rowA1 = (tid + 256) >> 2,  kcA1 = ((tid + 256) & 3) * 4;

    float acc[8][8];
#pragma unroll
    for (int i = 0; i < 8; i++)
#pragma unroll
        for (int j = 0; j < 8; j++) acc[i][j] = 0.f;

    float4 va0, va1, vb0, vb1;

    auto loadG = [&](int kk0) {
        const float* Asrc = A1; int acol = kk0;
        if (KPARTS == 2 && kk0 >= 128) { Asrc = A2; acol = kk0 - 128; }
        int gr0 = r0 + rowA0, gr1 = r0 + rowA1;
        va0 = make_float4(0.f, 0.f, 0.f, 0.f);
        va1 = make_float4(0.f, 0.f, 0.f, 0.f);
        if (gr0 < M) va0 = *(const float4*)(A1 == Asrc ? Asrc + (size_t)gr0 * F + acol + kcA0
                                                       : Asrc + (size_t)gr0 * F + acol + kcA0);
        if (gr1 < M) va1 = *(const float4*)(Asrc + (size_t)gr1 * F + acol + kcA1);
        vb0 = *(const float4*)(W + (size_t)rowA0 * K + kk0 + kcA0);
        vb1 = *(const float4*)(W + (size_t)rowA1 * K + kk0 + kcA1);
    };
    auto storeS = [&](int buf) {
        sA[buf][kcA0 + 0][rowA0] = va0.x; sA[buf][kcA0 + 1][rowA0] = va0.y;
        sA[buf][kcA0 + 2][rowA0] = va0.z; sA[buf][kcA0 + 3][rowA0] = va0.w;
        sA[buf][kcA1 + 0][rowA1] = va1.x; sA[buf][kcA1 + 1][rowA1] = va1.y;
        sA[buf][kcA1 + 2][rowA1] = va1.z; sA[buf][kcA1 + 3][rowA1] = va1.w;
        sB[buf][kcA0 + 0][rowA0] = vb0.x; sB[buf][kcA0 + 1][rowA0] = vb0.y;
        sB[buf][kcA0 + 2][rowA0] = vb0.z; sB[buf][kcA0 + 3][rowA0] = vb0.w;
        sB[buf][kcA1 + 0][rowA1] = vb1.x; sB[buf][kcA1 + 1][rowA1] = vb1.y;
        sB[buf][kcA1 + 2][rowA1] = vb1.z; sB[buf][kcA1 + 3][rowA1] = vb1.w;
    };

    loadG(0);
    storeS(0);
    __syncthreads();

    int buf = 0;
    for (int s = 0; s < NSTEP; ++s) {
        if (s + 1 < NSTEP) loadG((s + 1) * 16);
#pragma unroll
        for (int k = 0; k < 16; k++) {
            float4 a0 = *(const float4*)&sA[buf][k][ty * 8];
            float4 a1 = *(const float4*)&sA[buf][k][ty * 8 + 4];
            float4 b0 = *(const float4*)&sB[buf][k][tx * 8];
            float4 b1 = *(const float4*)&sB[buf][k][tx * 8 + 4];
            float ra[8] = { a0.x, a0.y, a0.z, a0.w, a1.x, a1.y, a1.z, a1.w };
            float rb[8] = { b0.x, b0.y, b0.z, b0.w, b1.x, b1.y, b1.z, b1.w };
#pragma unroll
            for (int i = 0; i < 8; i++)
#pragma unroll
                for (int j = 0; j < 8; j++)
                    acc[i][j] = fmaf(ra[i], rb[j], acc[i][j]);
        }
        if (s + 1 < NSTEP) {
            storeS(buf ^ 1);
            __syncthreads();
            buf ^= 1;
        }
    }

#pragma unroll
    for (int i = 0; i < 8; i++) {
        int gr = r0 + ty * 8 + i;
        if (gr >= M) continue;
#pragma unroll
        for (int j = 0; j < 8; j++) {
            int gc = tx * 8 + j;
            float v = acc[i][j] + (bias ? bias[gc] : 0.f);
            C[(size_t)gr * F + gc] = fmaxf(v, 0.f);
        }
    }
}

// ---------------- CSR-bucket build ----------------
__global__ void k_zerodeg(int M)
{
    int i = blockIdx.x * blockDim.x + threadIdx.x;
    if (i < M) g_deg[i] = 0;
}

__global__ void k_bucket(const int* __restrict__ esrc, const int* __restrict__ edst,
                         int E, int M)
{
    int t = blockIdx.x * blockDim.x + threadIdx.x;
    int half = E >> 1;
    if (t >= half) return;
#pragma unroll
    for (int q = 0; q < 2; q++) {
        int e = t + q * half;
        int d = edst[e];
        if (d >= M) continue;
        int s = esrc[e];
        int pos = atomicAdd(&g_deg[d], 1);
        if (pos < CAPD) g_bkt[(size_t)d * CAPD + pos] = s;
    }
}

// ---------------- gather-max: warp per dst node ----------------
__global__ void k_aggr(const float* __restrict__ y, float* __restrict__ aggr, int M)
{
    int warp = blockIdx.x * (blockDim.x >> 5) + (threadIdx.x >> 5);
    int lane = threadIdx.x & 31;
    if (warp >= M) return;
    int dv = g_deg[warp];
    if (dv > CAPD) dv = CAPD;
    const int* b = g_bkt + (size_t)warp * CAPD;
    float4 acc = ((const float4*)(y + (size_t)warp * F))[lane];
    int i = 0;
    for (; i + 1 < dv; i += 2) {
        int s0 = b[i], s1 = b[i + 1];
        float4 t0 = ((const float4*)(y + (size_t)s0 * F))[lane];
        float4 t1 = ((const float4*)(y + (size_t)s1 * F))[lane];
        acc.x = fmaxf(acc.x, fmaxf(t0.x, t1.x));
        acc.y = fmaxf(acc.y, fmaxf(t0.y, t1.y));
        acc.z = fmaxf(acc.z, fmaxf(t0.z, t1.z));
        acc.w = fmaxf(acc.w, fmaxf(t0.w, t1.w));
    }
    if (i < dv) {
        int s0 = b[i];
        float4 t0 = ((const float4*)(y + (size_t)s0 * F))[lane];
        acc.x = fmaxf(acc.x, t0.x);
        acc.y = fmaxf(acc.y, t0.y);
        acc.z = fmaxf(acc.z, t0.z);
        acc.w = fmaxf(acc.w, t0.w);
    }
    ((float4*)(aggr + (size_t)warp * F))[lane] = acc;
}

// ---------------- scores (wnorm fused) ----------------
__global__ void k_scores(const float* __restrict__ h, const float* __restrict__ w, int M)
{
    __shared__ float s_inv;
    int lane = threadIdx.x & 31;
    if (threadIdx.x < 32) {
        float4 b0 = ((const float4*)w)[lane];
        float sq = b0.x * b0.x + b0.y * b0.y + b0.z * b0.z + b0.w * b0.w;
        for (int o = 16; o > 0; o >>= 1) sq += __shfl_down_sync(0xffffffffu, sq, o);
        if (lane == 0) s_inv = rsqrtf(sq);
    }
    __syncthreads();
    int warp = blockIdx.x * (blockDim.x >> 5) + (threadIdx.x >> 5);
    if (warp >= M) return;
    float4 a = ((const float4*)(h + (size_t)warp * F))[lane];
    float4 b = ((const float4*)w)[lane];
    float d = a.x * b.x + a.y * b.y + a.z * b.z + a.w * b.w;
    for (int o = 16; o > 0; o >>= 1) d += __shfl_down_sync(0xffffffffu, d, o);
    if (lane == 0) g_s[warp] = d * s_inv;
}

// ---------------- per-graph exact radix select ----------------
__global__ void k_select(int n, int kk)
{
    int g = blockIdx.x;
    const float* sg = g_s + (size_t)g * n;
    __shared__ unsigned hist[256];
    __shared__ unsigned s_prefix, s_mask;
    __shared__ int s_need;
    if (threadIdx.x == 0) { s_prefix = 0; s_mask = 0; s_need = kk; }
    __syncthreads();
    for (int pass = 0; pass < 4; ++pass) {
        int shift = 24 - 8 * pass;
        if (threadIdx.x < 256) hist[threadIdx.x] = 0;
        __syncthreads();
        unsigned pre = s_prefix, msk = s_mask;
        for (int i = threadIdx.x; i < n; i += blockDim.x) {
            unsigned key = ordkey(sg[i]);
            if ((key & msk) == pre) atomicAdd(&hist[(key >> shift) & 255], 1u);
        }
        __syncthreads();
        if (threadIdx.x == 0) {
            int need = s_need;
            unsigned cum = 0;
            for (int b = 255; b >= 0; --b) {
                unsigned h = hist[b];
                if (cum + h >= (unsigned)need) {
                    s_need = need - (int)cum;
                    s_prefix = pre | ((unsigned)b << shift);
                    s_mask = msk | (255u << shift);
                    break;
                }
                cum += h;
            }
        }
        __syncthreads();
    }
    if (threadIdx.x == 0) { g_thr[g] = s_prefix; g_needeq[g] = s_need; }
}

__global__ void k_initpool(int Msize, int Mn)
{
    int i = blockIdx.x * blockDim.x + threadIdx.x;
    if (i < Msize) g_newpos[i] = Mn;
    if (i < BGR) { g_cnt[i] = 0; g_eqcnt[i] = 0; }
}

__global__ void k_compact(int M, int n, int kk)
{
    int v = blockIdx.x * blockDim.x + threadIdx.x;
    if (v >= M) return;
    int g = v / n;
    float sv = g_s[v];
    unsigned key = ordkey(sv);
    unsigned T = g_thr[g];
    bool keep = false;
    if (key > T) keep = true;
    else if (key == T && atomicAdd(&g_eqcnt[g], 1) < g_needeq[g]) keep = true;
    if (!keep) return;
    int pos = atomicAdd(&g_cnt[g], 1);
    int j = g * kk + pos;
    g_newpos[v] = j;
    g_gidx[j] = v;
    g_tanhv[j] = tanhf(sv);
}

__global__ void k_gather(const float* __restrict__ h, float* __restrict__ xnew, int Mn)
{
    int idx = blockIdx.x * blockDim.x + threadIdx.x;
    int j = idx >> 5, q = idx & 31;
    if (j >= Mn) return;
    float t = g_tanhv[j];
    float4 v = *(const float4*)(h + (size_t)g_gidx[j] * F + q * 4);
    v.x *= t; v.y *= t; v.z *= t; v.w *= t;
    *(float4*)(xnew + (size_t)j * F + q * 4) = v;
}

__global__ void k_remap(const int* __restrict__ es, const int* __restrict__ ed,
                        int* __restrict__ eo, int E, int Mn)
{
    int i = blockIdx.x * blockDim.x + threadIdx.x;
    if (i >= E) return;
    int s = g_newpos[es[i]];
    int d = g_newpos[ed[i]];
    if (s == Mn || d == Mn) { s = Mn; d = Mn; }
    eo[i] = s;
    eo[E + i] = d;
}

// ---------------- readout ----------------
__global__ void k_rpart(const float* __restrict__ x, int kk)
{
    int g = blockIdx.x / CH, c = blockIdx.x % CH;
    int rpc = kk / CH;
    int f = threadIdx.x;  // 128
    const float* base = x + ((size_t)g * kk + (size_t)c * rpc) * F + f;
    float vmax = -3.4e38f, vsum = 0.f;
    for (int r = 0; r < rpc; r++) {
        float v = base[(size_t)r * F];
        vmax = fmaxf(vmax, v);
        vsum += v;
    }
    float* p = g_part + (size_t)blockIdx.x * 2 * F;
    p[f] = vmax;
    p[F + f] = vsum;
}

__global__ void k_rfinal(int kk)
{
    int g = blockIdx.x;
    int f = threadIdx.x;  // 256
    const float* p = g_part + (size_t)g * CH * 2 * F;
    if (f < F) {
        float m = -3.4e38f;
        for (int c = 0; c < CH; c++) m = fmaxf(m, p[c * 2 * F + f]);
        g_z[g * 2 * F + f] += m;
    } else {
        float s = 0.f;
        for (int c = 0; c < CH; c++) s += p[c * 2 * F + f];
        g_z[g * 2 * F + f] += s / (float)kk;
    }
}

__global__ void k_zeroz()
{
    int i = blockIdx.x * blockDim.x + threadIdx.x;
    if (i < BGR * 2 * F) g_z[i] = 0.f;
}

// ---------------- final MLP + sigmoid ----------------
__global__ void k_mlp(const float* __restrict__ Wl1, const float* __restrict__ bl1,
                      const float* __restrict__ Wl2, const float* __restrict__ bl2,
                      const float* __restrict__ Wl3, const float* __restrict__ bl3,
                      float* __restrict__ out)
{
    __shared__ float sz[BGR][2 * F];
    __shared__ float h1[BGR][F];
    __shared__ float h2[BGR][64];
    int t = threadIdx.x;  // 256
    for (int i = t; i < BGR * 2 * F; i += 256) ((float*)sz)[i] = g_z[i];
    __syncthreads();
    for (int o = t; o < BGR * F; o += 256) {
        int g = o >> 7, r = o & 127;
        float a = bl1[r];
        const float* wr = Wl1 + (size_t)r * 2 * F;
        for (int c = 0; c < 2 * F; c++) a += sz[g][c] * wr[c];
        h1[g][r] = fmaxf(a, 0.f);
    }
    __syncthreads();
    for (int o = t; o < BGR * 64; o += 256) {
        int g = o >> 6, r = o & 63;
        float a = bl2[r];
        const float* wr = Wl2 + (size_t)r * F;
        for (int c = 0; c < F; c++) a += h1[g][c] * wr[c];
        h2[g][r] = fmaxf(a, 0.f);
    }
    __syncthreads();
    if (t < BGR) {
        float a = bl3[0];
        for (int c = 0; c < 64; c++) a += h2[t][c] * Wl3[c];
        out[t] = 1.f / (1.f + expf(-a));
    }
}

// ---------------- orchestration ----------------
extern "C" void kernel_launch(void* const* d_in, const int* in_sizes, int n_in,
                              void* d_out, int out_size)
{
    const float* x = (const float*)d_in[0];
    const int* ei = (const int*)d_in[1];
    const float* Wlin[3] = { (const float*)d_in[2], (const float*)d_in[6], (const float*)d_in[10] };
    const float* blin[3] = { (const float*)d_in[3], (const float*)d_in[7], (const float*)d_in[11] };
    const float* Wupd[3] = { (const float*)d_in[4], (const float*)d_in[8], (const float*)d_in[12] };
    const float* wp[3]   = { (const float*)d_in[5], (const float*)d_in[9], (const float*)d_in[13] };
    const float* Wl1 = (const float*)d_in[14];
    const float* bl1 = (const float*)d_in[15];
    const float* Wl2 = (const float*)d_in[16];
    const float* bl2 = (const float*)d_in[17];
    const float* Wl3 = (const float*)d_in[18];
    const float* bl3 = (const float*)d_in[19];

    float *yb, *ag, *h1p, *h2p;
    int *eA, *eB;
    cudaGetSymbolAddress((void**)&yb, g_y);
    cudaGetSymbolAddress((void**)&ag, g_aggr);
    cudaGetSymbolAddress((void**)&h1p, g_h1);
    cudaGetSymbolAddress((void**)&h2p, g_h2);
    cudaGetSymbolAddress((void**)&eA, g_eA);
    cudaGetSymbolAddress((void**)&eB, g_eB);

    const int Ms[3] = { 100000, 80000, 64000 };
    const int kks[3] = { 10000, 8000, 6400 };

    k_zeroz<<<8, 256>>>();

    const float* hin = x;
    const int* es = ei;
    const int* ed = ei + EMAX;

    for (int st = 0; st < 3; ++st) {
        int M = Ms[st];
        int gridG = (M + 127) / 128;

        k_gemm<1><<<gridG, 256>>>(hin, nullptr, Wlin[st], blin[st], yb, M);
        k_zerodeg<<<(M + 255) / 256, 256>>>(M);
        k_bucket<<<(EMAX / 2 + 255) / 256, 256>>>(es, ed, EMAX, M);
        k_aggr<<<(M + 7) / 8, 256>>>(yb, ag, M);
        k_gemm<2><<<gridG, 256>>>(ag, hin, Wupd[st], nullptr, h1p, M);

        int kk = kks[st], n = M / BGR, Mn = BGR * kk;
        k_scores<<<(M + 3) / 4, 128>>>(h1p, wp[st], M);
        k_select<<<BGR, 256>>>(n, kk);
        k_initpool<<<(M + 1 + 255) / 256, 256>>>(M + 1, Mn);
        k_compact<<<(M + 255) / 256, 256>>>(M, n, kk);
        k_gather<<<(Mn * 32 + 255) / 256, 256>>>(h1p, h2p, Mn);
        if (st < 2) {
            int* eo = (st == 0) ? eA : eB;
            k_remap<<<(EMAX + 255) / 256, 256>>>(es, ed, eo, EMAX, Mn);
            es = eo;
            ed = eo + EMAX;
        }

        k_rpart<<<BGR * CH, 128>>>(h2p, kk);
        k_rfinal<<<BGR, 256>>>(kk);

        hin = h2p;
    }

    k_mlp<<<1, 256>>>(Wl1, bl1, Wl2, bl2, Wl3, bl3, (float*)d_out);
}